// round 15
// baseline (speedup 1.0000x reference)
#include <cuda_runtime.h>
#include <cuda_bf16.h>
#include <math.h>
#include <cstdint>

#define S_LEN  2048
#define BATCH  2
#define DMODEL 1024
#define NHEADS 16
#define DK     64
#define MTOT   (BATCH * S_LEN)   // 4096

// ---------------- scratch (static device allocations; no cudaMalloc) -----
__device__ float2 g_rope[S_LEN * (DK / 2)];
__device__ __nv_bfloat16 g_xh[(size_t)MTOT * DMODEL];
__device__ __nv_bfloat16 g_xl[(size_t)MTOT * DMODEL];
__device__ __nv_bfloat16 g_qh[(size_t)MTOT * DMODEL];
__device__ __nv_bfloat16 g_ql[(size_t)MTOT * DMODEL];
__device__ __nv_bfloat16 g_kh[(size_t)MTOT * DMODEL];
__device__ __nv_bfloat16 g_kl[(size_t)MTOT * DMODEL];
__device__ __nv_bfloat16 g_vh[(size_t)MTOT * DMODEL];
__device__ __nv_bfloat16 g_vl[(size_t)MTOT * DMODEL];
__device__ __nv_bfloat16 g_oh[(size_t)MTOT * DMODEL];
__device__ __nv_bfloat16 g_ol[(size_t)MTOT * DMODEL];
__device__ __nv_bfloat16 g_wh[4][(size_t)DMODEL * DMODEL];
__device__ __nv_bfloat16 g_wl[4][(size_t)DMODEL * DMODEL];

// ---------------- helpers -------------------------------------------------
__device__ __forceinline__ uint32_t smem_u32(const void* p) {
    uint32_t a;
    asm("{ .reg .u64 t; cvta.to.shared.u64 t, %1; cvt.u32.u64 %0, t; }"
        : "=r"(a) : "l"(p));
    return a;
}
__device__ __forceinline__ void ldmat4(uint32_t* r, uint32_t addr) {
    asm volatile("ldmatrix.sync.aligned.m8n8.x4.shared.b16 {%0,%1,%2,%3}, [%4];"
                 : "=r"(r[0]), "=r"(r[1]), "=r"(r[2]), "=r"(r[3]) : "r"(addr));
}
__device__ __forceinline__ void ldmat4t(uint32_t* r, uint32_t addr) {
    asm volatile("ldmatrix.sync.aligned.m8n8.x4.trans.shared.b16 {%0,%1,%2,%3}, [%4];"
                 : "=r"(r[0]), "=r"(r[1]), "=r"(r[2]), "=r"(r[3]) : "r"(addr));
}
__device__ __forceinline__ void mma_bf16(float* d, const uint32_t* a,
                                         const uint32_t* b) {
    asm volatile(
        "mma.sync.aligned.m16n8k16.row.col.f32.bf16.bf16.f32 "
        "{%0,%1,%2,%3}, {%4,%5,%6,%7}, {%8,%9}, {%0,%1,%2,%3};"
        : "+f"(d[0]), "+f"(d[1]), "+f"(d[2]), "+f"(d[3])
        : "r"(a[0]), "r"(a[1]), "r"(a[2]), "r"(a[3]), "r"(b[0]), "r"(b[1]));
}
__device__ __forceinline__ uint32_t pack_bf16(__nv_bfloat16 lo, __nv_bfloat16 hi) {
    __nv_bfloat162 t(lo, hi);
    return *(uint32_t*)&t;
}
__device__ __forceinline__ uint32_t pack_bf16f(float lo, float hi) {
    uint32_t r;
    asm("cvt.rn.bf16x2.f32 %0, %1, %2;" : "=r"(r) : "f"(hi), "f"(lo));
    return r;
}
#define CP16(sm, gp) \
    asm volatile("cp.async.cg.shared.global [%0], [%1], 16;" \
                 :: "r"(sm), "l"(gp))
#define CP_COMMIT() asm volatile("cp.async.commit_group;" ::: "memory")
#define CP_WAIT1()  asm volatile("cp.async.wait_group 1;" ::: "memory")
#define CP_WAIT0()  asm volatile("cp.async.wait_group 0;" ::: "memory")

// ========================================================================
// split: fp32 -> bf16 hi + bf16 lo
// ========================================================================
__global__ void split_kernel(const float* __restrict__ src,
                             __nv_bfloat16* __restrict__ hi,
                             __nv_bfloat16* __restrict__ lo, int n4) {
    int i = blockIdx.x * blockDim.x + threadIdx.x;
    if (i >= n4) return;
    float4 v = ((const float4*)src)[i];
    __nv_bfloat16 h[4], l[4];
    float f[4] = {v.x, v.y, v.z, v.w};
#pragma unroll
    for (int j = 0; j < 4; j++) {
        h[j] = __float2bfloat16_rn(f[j]);
        l[j] = __float2bfloat16_rn(f[j] - __bfloat162float(h[j]));
    }
    ((uint2*)hi)[i] = *(uint2*)h;
    ((uint2*)lo)[i] = *(uint2*)l;
}

// ========================================================================
// RoPE table
// ========================================================================
__global__ void rope_table_kernel() {
    int idx = blockIdx.x * blockDim.x + threadIdx.x;
    if (idx >= S_LEN * (DK / 2)) return;
    int s = idx >> 5;
    int i = idx & 31;
    float freq = 1.0f / powf(10000.0f, (float)(2 * i) / 64.0f);
    float ang  = (float)s * freq;
    double a   = (double)ang;
    g_rope[idx] = make_float2((float)cos(a), (float)sin(a));
}

// ========================================================================
// bf16 HMMA GEMM, 2-stage cp.async pipeline.
// Epilogue modes: 0 = fp32 store, 1 = rope + split, 2 = split.
// ========================================================================
#define GST   40960
#define GT_AH 0
#define GT_AL 10240
#define GT_BH 20480
#define GT_BL 30720

struct GemmArgs {
    const __nv_bfloat16 *Ah, *Al;
    const __nv_bfloat16 *Bh[3], *Bl[3];
    float* Cf[3];
    __nv_bfloat16 *Ch[3], *Cl[3];
    int mode[3];
};

__global__ __launch_bounds__(256) void gemm_hmma(GemmArgs args) {
    extern __shared__ char smg[];
    const uint32_t smb = smem_u32(smg);

    const int z = blockIdx.z;
    const __nv_bfloat16* Ahg = args.Ah;
    const __nv_bfloat16* Alg = args.Al;
    const __nv_bfloat16* Bhg = args.Bh[z];
    const __nv_bfloat16* Blg = args.Bl[z];
    const int mode = args.mode[z];

    const int tid  = threadIdx.x;
    const int lane = tid & 31;
    const int wid  = tid >> 5;
    const int wm   = wid >> 2;
    const int wn   = wid & 3;
    const int bm   = blockIdx.y * 128;
    const int bn   = blockIdx.x * 128;

    const int l7  = lane & 7;
    const int l8  = (lane >> 3) & 1;
    const int l16 = lane >> 4;
    const uint32_t aoff = (uint32_t)((wm * 64 + l7 + l8 * 8) * 80 + l16 * 16);
    const uint32_t boff = (uint32_t)((wn * 32 + l16 * 8 + l7) * 80 + l8 * 16);

    float acc[4][4][4];
#pragma unroll
    for (int mt = 0; mt < 4; mt++)
#pragma unroll
        for (int nt = 0; nt < 4; nt++)
#pragma unroll
            for (int e = 0; e < 4; e++) acc[mt][nt][e] = 0.f;

    // cp.async indexing: f = tid + p*256 (p=0,1): r = f>>2 (0..127), cg = f&3
    const int r0 = (tid + 0)   >> 2, cg0 = (tid + 0)   & 3;
    const int r1 = (tid + 256) >> 2, cg1 = (tid + 256) & 3;
    const uint32_t so0 = (uint32_t)(r0 * 80 + cg0 * 16);
    const uint32_t so1 = (uint32_t)(r1 * 80 + cg1 * 16);

#define G_ASYNC(st, kbase)                                                    \
    do {                                                                      \
        const uint32_t sb_ = smb + (uint32_t)(st) * GST;                      \
        const size_t ga0 = (size_t)(bm + r0) * DMODEL + (kbase) + cg0 * 8;    \
        const size_t ga1 = (size_t)(bm + r1) * DMODEL + (kbase) + cg1 * 8;    \
        const size_t gb0 = (size_t)(bn + r0) * DMODEL + (kbase) + cg0 * 8;    \
        const size_t gb1 = (size_t)(bn + r1) * DMODEL + (kbase) + cg1 * 8;    \
        CP16(sb_ + GT_AH + so0, Ahg + ga0); CP16(sb_ + GT_AH + so1, Ahg + ga1); \
        CP16(sb_ + GT_AL + so0, Alg + ga0); CP16(sb_ + GT_AL + so1, Alg + ga1); \
        CP16(sb_ + GT_BH + so0, Bhg + gb0); CP16(sb_ + GT_BH + so1, Bhg + gb1); \
        CP16(sb_ + GT_BL + so0, Blg + gb0); CP16(sb_ + GT_BL + so1, Blg + gb1); \
    } while (0)

    G_ASYNC(0, 0);
    CP_COMMIT();

    for (int c = 0; c < 32; c++) {
        const bool more = (c < 31);
        if (more) {
            G_ASYNC((c + 1) & 1, (c + 1) * 32);
            CP_COMMIT();
            CP_WAIT1();
        } else {
            CP_WAIT0();
        }
        __syncthreads();
        const uint32_t sb = smb + (uint32_t)(c & 1) * GST;

#pragma unroll
        for (int ks = 0; ks < 2; ks++) {
            const uint32_t kso = ks * 32;
            uint32_t Ahf[4][4], Alf[4][4], Bhf[4][2], Blf[4][2];
#pragma unroll
            for (int mt = 0; mt < 4; mt++) {
                const uint32_t ao = aoff + mt * (16 * 80) + kso;
                ldmat4(Ahf[mt], sb + GT_AH + ao);
                ldmat4(Alf[mt], sb + GT_AL + ao);
            }
#pragma unroll
            for (int np = 0; np < 2; np++) {
                const uint32_t bo = boff + np * (16 * 80) + kso;
                uint32_t t[4];
                ldmat4(t, sb + GT_BH + bo);
                Bhf[np * 2][0] = t[0]; Bhf[np * 2][1] = t[1];
                Bhf[np * 2 + 1][0] = t[2]; Bhf[np * 2 + 1][1] = t[3];
                ldmat4(t, sb + GT_BL + bo);
                Blf[np * 2][0] = t[0]; Blf[np * 2][1] = t[1];
                Blf[np * 2 + 1][0] = t[2]; Blf[np * 2 + 1][1] = t[3];
            }
#pragma unroll
            for (int mt = 0; mt < 4; mt++)
#pragma unroll
                for (int nt = 0; nt < 4; nt++) {
                    mma_bf16(acc[mt][nt], Ahf[mt], Bhf[nt]);
                    mma_bf16(acc[mt][nt], Ahf[mt], Blf[nt]);
                    mma_bf16(acc[mt][nt], Alf[mt], Bhf[nt]);
                }
        }
        __syncthreads();
    }

    const int g   = lane >> 2;
    const int tig = lane & 3;
#pragma unroll
    for (int mt = 0; mt < 4; mt++) {
        const int row = bm + wm * 64 + mt * 16 + g;
#pragma unroll
        for (int nt = 0; nt < 4; nt++) {
            const int col = bn + wn * 32 + nt * 8 + tig * 2;
            float e0 = acc[mt][nt][0], o0 = acc[mt][nt][1];
            float e1 = acc[mt][nt][2], o1 = acc[mt][nt][3];
            if (mode == 0) {
                *(float2*)(args.Cf[z] + (size_t)row * DMODEL + col) =
                    make_float2(e0, o0);
                *(float2*)(args.Cf[z] + (size_t)(row + 8) * DMODEL + col) =
                    make_float2(e1, o1);
            } else {
                if (mode == 1) {
                    const int i = (col & 63) >> 1;
                    float2 c0 = g_rope[((row & (S_LEN - 1)) << 5) + i];
                    float2 c1 = g_rope[(((row + 8) & (S_LEN - 1)) << 5) + i];
                    float te = e0 * c0.x - o0 * c0.y;
                    o0 = e0 * c0.y + o0 * c0.x; e0 = te;
                    te = e1 * c1.x - o1 * c1.y;
                    o1 = e1 * c1.y + o1 * c1.x; e1 = te;
                }
                __nv_bfloat16 he0 = __float2bfloat16_rn(e0);
                __nv_bfloat16 ho0 = __float2bfloat16_rn(o0);
                __nv_bfloat16 he1 = __float2bfloat16_rn(e1);
                __nv_bfloat16 ho1 = __float2bfloat16_rn(o1);
                uint32_t* H = (uint32_t*)(args.Ch[z] + (size_t)row * DMODEL + col);
                uint32_t* L = (uint32_t*)(args.Cl[z] + (size_t)row * DMODEL + col);
                *H = pack_bf16(he0, ho0);
                *L = pack_bf16f(e0 - __bfloat162float(he0),
                                o0 - __bfloat162float(ho0));
                H = (uint32_t*)(args.Ch[z] + (size_t)(row + 8) * DMODEL + col);
                L = (uint32_t*)(args.Cl[z] + (size_t)(row + 8) * DMODEL + col);
                *H = pack_bf16(he1, ho1);
                *L = pack_bf16f(e1 - __bfloat162float(he1),
                                o1 - __bfloat162float(ho1));
            }
        }
    }
#undef G_ASYNC
}

// ========================================================================
// Flash attention, bf16 HMMA 3-term, causal. BM=128, BN=64, 256 thr,
// 2-stage cp.async K/V pipeline. Q staged via stage-0 smem (proven loop).
// ========================================================================
#define FLDB 144
#define FST  36864
#define FT_KH 0
#define FT_KL 9216
#define FT_VH 18432
#define FT_VL 27648

__global__ __launch_bounds__(256) void flash_hmma(
    const __nv_bfloat16* __restrict__ Qhg, const __nv_bfloat16* __restrict__ Qlg,
    const __nv_bfloat16* __restrict__ Khg, const __nv_bfloat16* __restrict__ Klg,
    const __nv_bfloat16* __restrict__ Vhg, const __nv_bfloat16* __restrict__ Vlg,
    __nv_bfloat16* __restrict__ Ohg, __nv_bfloat16* __restrict__ Olg) {
    extern __shared__ char smf[];
    const uint32_t smb = smem_u32(smf);

    const int qt  = gridDim.x - 1 - blockIdx.x;
    const int h   = blockIdx.y;
    const int b   = blockIdx.z;
    const int tid = threadIdx.x;
    const int lane = tid & 31;
    const int w    = tid >> 5;
    const size_t base = ((size_t)b * S_LEN) * DMODEL + h * DK;
    const int q0 = qt * 128;
    const int ktmax = 2 * qt + 1;

    const int l7  = lane & 7;
    const int l8  = (lane >> 3) & 1;
    const int l16 = lane >> 4;
    const int g   = lane >> 2;
    const int tig = lane & 3;

    // ---- stage Q (hi then lo) via stage-0 region, extract A-frags ----
    // Q tile: 128 rows x 64 bf16 (128 B). f = tid + p*256 in [0,1024):
    // r = f>>3 in [0,128), c = f&7 (16B column group).
    uint32_t qha[4][4], qla[4][4];
    {
        const uint32_t ao = (uint32_t)((w * 16 + l7 + l8 * 8) * FLDB + l16 * 16);
#pragma unroll
        for (int p = 0; p < 4; p++) {
            int f = tid + p * 256;
            int r = f >> 3, c = f & 7;
            *(uint4*)(smf + r * FLDB + c * 16) =
                *(const uint4*)(Qhg + base + (size_t)(q0 + r) * DMODEL + c * 8);
        }
        __syncthreads();
#pragma unroll
        for (int ks = 0; ks < 4; ks++) ldmat4(qha[ks], smb + ao + ks * 32);
        __syncthreads();
#pragma unroll
        for (int p = 0; p < 4; p++) {
            int f = tid + p * 256;
            int r = f >> 3, c = f & 7;
            *(uint4*)(smf + r * FLDB + c * 16) =
                *(const uint4*)(Qlg + base + (size_t)(q0 + r) * DMODEL + c * 8);
        }
        __syncthreads();
#pragma unroll
        for (int ks = 0; ks < 4; ks++) ldmat4(qla[ks], smb + ao + ks * 32);
        __syncthreads();
    }

    // cp.async indexing: per tile f = tid + p*256 (p=0,1): r=f>>3(0..63), c=f&7
    const int fr0 = (tid + 0)   >> 3, fc0 = (tid + 0)   & 7;
    const int fr1 = (tid + 256) >> 3, fc1 = (tid + 256) & 7;
    const uint32_t fo0 = (uint32_t)(fr0 * FLDB + fc0 * 16);
    const uint32_t fo1 = (uint32_t)(fr1 * FLDB + fc1 * 16);

#define F_ASYNC(st, k0v)                                                      \
    do {                                                                      \
        const uint32_t sb_ = smb + (uint32_t)(st) * FST;                      \
        const size_t gk0 = base + (size_t)((k0v) + fr0) * DMODEL + fc0 * 8;   \
        const size_t gk1 = base + (size_t)((k0v) + fr1) * DMODEL + fc1 * 8;   \
        CP16(sb_ + FT_KH + fo0, Khg + gk0); CP16(sb_ + FT_KH + fo1, Khg + gk1); \
        CP16(sb_ + FT_KL + fo0, Klg + gk0); CP16(sb_ + FT_KL + fo1, Klg + gk1); \
        CP16(sb_ + FT_VH + fo0, Vhg + gk0); CP16(sb_ + FT_VH + fo1, Vhg + gk1); \
        CP16(sb_ + FT_VL + fo0, Vlg + gk0); CP16(sb_ + FT_VL + fo1, Vlg + gk1); \
    } while (0)

    F_ASYNC(0, 0);
    CP_COMMIT();

    float o[8][4];
#pragma unroll
    for (int dt = 0; dt < 8; dt++)
#pragma unroll
        for (int e = 0; e < 4; e++) o[dt][e] = 0.f;
    float m0 = -INFINITY, m1 = -INFINITY, li0 = 0.f, li1 = 0.f;

    const uint32_t bo_k = (uint32_t)((l16 * 8 + l7) * FLDB + l8 * 16);
    const uint32_t bo_v = (uint32_t)((l8 * 8 + l7) * FLDB + l16 * 16);
    const int rowb = q0 + 16 * w;

    for (int kt = 0; kt <= ktmax; kt++) {
        const int k0 = kt * 64;
        const bool more = (kt < ktmax);
        if (more) {
            F_ASYNC((kt + 1) & 1, k0 + 64);
            CP_COMMIT();
            CP_WAIT1();
        } else {
            CP_WAIT0();
        }
        __syncthreads();
        const uint32_t sb = smb + (uint32_t)(kt & 1) * FST;

        if (k0 <= rowb + 15) {
            // ---- S = Q K^T (3-term) ----
            float s[8][4];
#pragma unroll
            for (int nt = 0; nt < 8; nt++)
#pragma unroll
                for (int e = 0; e < 4; e++) s[nt][e] = 0.f;

#pragma unroll
            for (int ks = 0; ks < 4; ks++) {
#pragma unroll
                for (int np = 0; np < 4; np++) {
                    uint32_t th[4], tl[4];
                    const uint32_t bo = bo_k + np * (16 * FLDB) + ks * 32;
                    ldmat4(th, sb + FT_KH + bo);
                    ldmat4(tl, sb + FT_KL + bo);
                    mma_bf16(s[2 * np],     qha[ks], th);
                    mma_bf16(s[2 * np],     qha[ks], tl);
                    mma_bf16(s[2 * np],     qla[ks], th);
                    mma_bf16(s[2 * np + 1], qha[ks], th + 2);
                    mma_bf16(s[2 * np + 1], qha[ks], tl + 2);
                    mma_bf16(s[2 * np + 1], qla[ks], th + 2);
                }
            }

            // ---- softmax ----
            const bool diag = (k0 + 63 > rowb);
            const int row0 = rowb + g, row1 = row0 + 8;
            float mx0 = -INFINITY, mx1 = -INFINITY;
#pragma unroll
            for (int nt = 0; nt < 8; nt++) {
                const int c0 = k0 + nt * 8 + 2 * tig;
#pragma unroll
                for (int e = 0; e < 4; e++) s[nt][e] *= 0.125f;
                if (diag) {
                    if (c0     > row0) s[nt][0] = -INFINITY;
                    if (c0 + 1 > row0) s[nt][1] = -INFINITY;
                    if (c0     > row1) s[nt][2] = -INFINITY;
                    if (c0 + 1 > row1) s[nt][3] = -INFINITY;
                }
                mx0 = fmaxf(mx0, fmaxf(s[nt][0], s[nt][1]));
                mx1 = fmaxf(mx1, fmaxf(s[nt][2], s[nt][3]));
            }
#pragma unroll
            for (int off = 1; off <= 2; off <<= 1) {
                mx0 = fmaxf(mx0, __shfl_xor_sync(0xffffffffu, mx0, off));
                mx1 = fmaxf(mx1, __shfl_xor_sync(0xffffffffu, mx1, off));
            }
            const float nm0 = fmaxf(m0, mx0), nm1 = fmaxf(m1, mx1);
            const float cr0 = __expf(m0 - nm0), cr1 = __expf(m1 - nm1);
            m0 = nm0; m1 = nm1;
            float rs0 = 0.f, rs1 = 0.f;
#pragma unroll
            for (int nt = 0; nt < 8; nt++) {
                s[nt][0] = __expf(s[nt][0] - nm0);
                s[nt][1] = __expf(s[nt][1] - nm0);
                s[nt][2] = __expf(s[nt][2] - nm1);
                s[nt][3] = __expf(s[nt][3] - nm1);
                rs0 += s[nt][0] + s[nt][1];
                rs1 += s[nt][2] + s[nt][3];
            }
#pragma unroll
            for (int off = 1; off <= 2; off <<= 1) {
                rs0 += __shfl_xor_sync(0xffffffffu, rs0, off);
                rs1 += __shfl_xor_sync(0xffffffffu, rs1, off);
            }
            li0 = li0 * cr0 + rs0;
            li1 = li1 * cr1 + rs1;
#pragma unroll
            for (int dt = 0; dt < 8; dt++) {
                o[dt][0] *= cr0; o[dt][1] *= cr0;
                o[dt][2] *= cr1; o[dt][3] *= cr1;
            }

            // ---- O += P V (3-term) ----
#pragma unroll
            for (int j = 0; j < 4; j++) {
                uint32_t pha[4], pla[4];
#pragma unroll
                for (int half = 0; half < 2; half++) {
                    const int nt = 2 * j + half;
                    __nv_bfloat16 b0 = __float2bfloat16_rn(s[nt][0]);
                    __nv_bfloat16 b1 = __float2bfloat16_rn(s[nt][1]);
                    __nv_bfloat16 b2 = __float2bfloat16_rn(s[nt][2]);
                    __nv_bfloat16 b3 = __float2bfloat16_rn(s[nt][3]);
                    pha[2 * half + 0] = pack_bf16(b0, b1);
                    pha[2 * half + 1] = pack_bf16(b2, b3);
                    pla[2 * half + 0] = pack_bf16f(s[nt][0] - __bfloat162float(b0),
                                                   s[nt][1] - __bfloat162float(b1));
                    pla[2 * half + 1] = pack_bf16f(s[nt][2] - __bfloat162float(b2),
                                                   s[nt][3] - __bfloat162float(b3));
                }
#pragma unroll
                for (int np = 0; np < 4; np++) {
                    uint32_t tvh[4], tvl[4];
                    const uint32_t bo = bo_v + j * (16 * FLDB) + np * 32;
                    ldmat4t(tvh, sb + FT_VH + bo);
                    ldmat4t(tvl, sb + FT_VL + bo);
                    mma_bf16(o[2 * np],     pha, tvh);
                    mma_bf16(o[2 * np],     pha, tvl);
                    mma_bf16(o[2 * np],     pla, tvh);
                    mma_bf16(o[2 * np + 1], pha, tvh + 2);
                    mma_bf16(o[2 * np + 1], pha, tvl + 2);
                    mma_bf16(o[2 * np + 1], pla, tvh + 2);
                }
            }
        }
        __syncthreads();
    }

    // ---- epilogue ----
    const float inv0 = 1.0f / li0, inv1 = 1.0f / li1;
    const int row0 = rowb + g;
#pragma unroll
    for (int dt = 0; dt < 8; dt++) {
        const int col = dt * 8 + tig * 2;
        float e0 = o[dt][0] * inv0, o0 = o[dt][1] * inv0;
        float e1 = o[dt][2] * inv1, o1 = o[dt][3] * inv1;
        __nv_bfloat16 he0 = __float2bfloat16_rn(e0);
        __nv_bfloat16 ho0 = __float2bfloat16_rn(o0);
        __nv_bfloat16 he1 = __float2bfloat16_rn(e1);
        __nv_bfloat16 ho1 = __float2bfloat16_rn(o1);
        *(uint32_t*)(Ohg + base + (size_t)row0 * DMODEL + col) =
            pack_bf16(he0, ho0);
        *(uint32_t*)(Olg + base + (size_t)row0 * DMODEL + col) =
            pack_bf16f(e0 - __bfloat162float(he0), o0 - __bfloat162float(ho0));
        *(uint32_t*)(Ohg + base + (size_t)(row0 + 8) * DMODEL + col) =
            pack_bf16(he1, ho1);
        *(uint32_t*)(Olg + base + (size_t)(row0 + 8) * DMODEL + col) =
            pack_bf16f(e1 - __bfloat162float(he1), o1 - __bfloat162float(ho1));
    }
#undef F_ASYNC
}

// ========================================================================
extern "C" void kernel_launch(void* const* d_in, const int* in_sizes, int n_in,
                              void* d_out, int out_size) {
    (void)in_sizes; (void)n_in; (void)out_size;
    const float* x  = (const float*)d_in[0];
    const float* W[4] = {(const float*)d_in[1], (const float*)d_in[2],
                         (const float*)d_in[3], (const float*)d_in[4]};
    float* out = (float*)d_out;

    __nv_bfloat16 *xh, *xl, *qh, *ql, *kh, *kl, *vh, *vl, *oh, *ol, *wh, *wl;
    cudaGetSymbolAddress((void**)&xh, g_xh);
    cudaGetSymbolAddress((void**)&xl, g_xl);
    cudaGetSymbolAddress((void**)&qh, g_qh);
    cudaGetSymbolAddress((void**)&ql, g_ql);
    cudaGetSymbolAddress((void**)&kh, g_kh);
    cudaGetSymbolAddress((void**)&kl, g_kl);
    cudaGetSymbolAddress((void**)&vh, g_vh);
    cudaGetSymbolAddress((void**)&vl, g_vl);
    cudaGetSymbolAddress((void**)&oh, g_oh);
    cudaGetSymbolAddress((void**)&ol, g_ol);
    cudaGetSymbolAddress((void**)&wh, g_wh);
    cudaGetSymbolAddress((void**)&wl, g_wl);

    const int NX4 = MTOT * DMODEL / 4;
    const int NW4 = DMODEL * DMODEL / 4;
    split_kernel<<<NX4 / 256, 256>>>(x, xh, xl, NX4);
    for (int i = 0; i < 4; i++)
        split_kernel<<<NW4 / 256, 256>>>(W[i], wh + (size_t)i * DMODEL * DMODEL,
                                         wl + (size_t)i * DMODEL * DMODEL, NW4);
    rope_table_kernel<<<(S_LEN * (DK / 2) + 255) / 256, 256>>>();

    cudaFuncSetAttribute(gemm_hmma,
                         cudaFuncAttributeMaxDynamicSharedMemorySize, 2 * GST);
    cudaFuncSetAttribute(flash_hmma,
                         cudaFuncAttributeMaxDynamicSharedMemorySize, 2 * FST);

    GemmArgs qkv = {};
    qkv.Ah = xh; qkv.Al = xl;
    for (int i = 0; i < 3; i++) {
        qkv.Bh[i] = wh + (size_t)i * DMODEL * DMODEL;
        qkv.Bl[i] = wl + (size_t)i * DMODEL * DMODEL;
    }
    qkv.Ch[0] = qh; qkv.Cl[0] = ql; qkv.mode[0] = 1;
    qkv.Ch[1] = kh; qkv.Cl[1] = kl; qkv.mode[1] = 1;
    qkv.Ch[2] = vh; qkv.Cl[2] = vl; qkv.mode[2] = 2;
    dim3 gq(DMODEL / 128, MTOT / 128, 3);
    gemm_hmma<<<gq, 256, 2 * GST>>>(qkv);

    flash_hmma<<<dim3(S_LEN / 128, NHEADS, BATCH), 256, 2 * FST>>>(
        qh, ql, kh, kl, vh, vl, oh, ol);

    GemmArgs op = {};
    op.Ah = oh; op.Al = ol;
    op.Bh[0] = wh + 3 * (size_t)DMODEL * DMODEL;
    op.Bl[0] = wl + 3 * (size_t)DMODEL * DMODEL;
    op.Cf[0] = out; op.mode[0] = 0;
    dim3 go(DMODEL / 128, MTOT / 128, 1);
    gemm_hmma<<<go, 256, 2 * GST>>>(op);
}

// round 16
// speedup vs baseline: 1.0349x; 1.0349x over previous
#include <cuda_runtime.h>
#include <cuda_bf16.h>
#include <math.h>
#include <cstdint>

#define S_LEN  2048
#define BATCH  2
#define DMODEL 1024
#define NHEADS 16
#define DK     64
#define MTOT   (BATCH * S_LEN)   // 4096

// ---------------- scratch (static device allocations; no cudaMalloc) -----
__device__ float2 g_rope[S_LEN * (DK / 2)];
__device__ __nv_bfloat16 g_xh[(size_t)MTOT * DMODEL];
__device__ __nv_bfloat16 g_xl[(size_t)MTOT * DMODEL];
__device__ __nv_bfloat16 g_qh[(size_t)MTOT * DMODEL];
__device__ __nv_bfloat16 g_ql[(size_t)MTOT * DMODEL];
__device__ __nv_bfloat16 g_kh[(size_t)MTOT * DMODEL];
__device__ __nv_bfloat16 g_kl[(size_t)MTOT * DMODEL];
__device__ __nv_bfloat16 g_vh[(size_t)MTOT * DMODEL];
__device__ __nv_bfloat16 g_vl[(size_t)MTOT * DMODEL];
__device__ __nv_bfloat16 g_oh[(size_t)MTOT * DMODEL];
__device__ __nv_bfloat16 g_ol[(size_t)MTOT * DMODEL];
__device__ __nv_bfloat16 g_wh[4][(size_t)DMODEL * DMODEL];
__device__ __nv_bfloat16 g_wl[4][(size_t)DMODEL * DMODEL];

// ---------------- helpers -------------------------------------------------
__device__ __forceinline__ uint32_t smem_u32(const void* p) {
    uint32_t a;
    asm("{ .reg .u64 t; cvta.to.shared.u64 t, %1; cvt.u32.u64 %0, t; }"
        : "=r"(a) : "l"(p));
    return a;
}
__device__ __forceinline__ void ldmat4(uint32_t* r, uint32_t addr) {
    asm volatile("ldmatrix.sync.aligned.m8n8.x4.shared.b16 {%0,%1,%2,%3}, [%4];"
                 : "=r"(r[0]), "=r"(r[1]), "=r"(r[2]), "=r"(r[3]) : "r"(addr));
}
__device__ __forceinline__ void ldmat4t(uint32_t* r, uint32_t addr) {
    asm volatile("ldmatrix.sync.aligned.m8n8.x4.trans.shared.b16 {%0,%1,%2,%3}, [%4];"
                 : "=r"(r[0]), "=r"(r[1]), "=r"(r[2]), "=r"(r[3]) : "r"(addr));
}
__device__ __forceinline__ void mma_bf16(float* d, const uint32_t* a,
                                         const uint32_t* b) {
    asm volatile(
        "mma.sync.aligned.m16n8k16.row.col.f32.bf16.bf16.f32 "
        "{%0,%1,%2,%3}, {%4,%5,%6,%7}, {%8,%9}, {%0,%1,%2,%3};"
        : "+f"(d[0]), "+f"(d[1]), "+f"(d[2]), "+f"(d[3])
        : "r"(a[0]), "r"(a[1]), "r"(a[2]), "r"(a[3]), "r"(b[0]), "r"(b[1]));
}
__device__ __forceinline__ uint32_t pack_bf16(__nv_bfloat16 lo, __nv_bfloat16 hi) {
    __nv_bfloat162 t(lo, hi);
    return *(uint32_t*)&t;
}
__device__ __forceinline__ uint32_t pack_bf16f(float lo, float hi) {
    uint32_t r;
    asm("cvt.rn.bf16x2.f32 %0, %1, %2;" : "=r"(r) : "f"(hi), "f"(lo));
    return r;
}
#define CP16(sm, gp) \
    asm volatile("cp.async.cg.shared.global [%0], [%1], 16;" \
                 :: "r"(sm), "l"(gp))
#define CP_COMMIT() asm volatile("cp.async.commit_group;" ::: "memory")
#define CP_WAIT1()  asm volatile("cp.async.wait_group 1;" ::: "memory")
#define CP_WAIT0()  asm volatile("cp.async.wait_group 0;" ::: "memory")

// ========================================================================
// split: fp32 -> bf16 hi + bf16 lo  (single tensor)
// ========================================================================
__global__ void split_kernel(const float* __restrict__ src,
                             __nv_bfloat16* __restrict__ hi,
                             __nv_bfloat16* __restrict__ lo, int n4) {
    int i = blockIdx.x * blockDim.x + threadIdx.x;
    if (i >= n4) return;
    float4 v = ((const float4*)src)[i];
    __nv_bfloat16 h[4], l[4];
    float f[4] = {v.x, v.y, v.z, v.w};
#pragma unroll
    for (int j = 0; j < 4; j++) {
        h[j] = __float2bfloat16_rn(f[j]);
        l[j] = __float2bfloat16_rn(f[j] - __bfloat162float(h[j]));
    }
    ((uint2*)hi)[i] = *(uint2*)h;
    ((uint2*)lo)[i] = *(uint2*)l;
}

// fused 4-way split (weights), blockIdx.y selects tensor
struct Split4Args { const float* src[4]; __nv_bfloat16 *hi[4], *lo[4]; };
__global__ void split4_kernel(Split4Args a, int n4) {
    int i = blockIdx.x * blockDim.x + threadIdx.x;
    if (i >= n4) return;
    const int z = blockIdx.y;
    float4 v = ((const float4*)a.src[z])[i];
    __nv_bfloat16 h[4], l[4];
    float f[4] = {v.x, v.y, v.z, v.w};
#pragma unroll
    for (int j = 0; j < 4; j++) {
        h[j] = __float2bfloat16_rn(f[j]);
        l[j] = __float2bfloat16_rn(f[j] - __bfloat162float(h[j]));
    }
    ((uint2*)a.hi[z])[i] = *(uint2*)h;
    ((uint2*)a.lo[z])[i] = *(uint2*)l;
}

// ========================================================================
// RoPE table
// ========================================================================
__global__ void rope_table_kernel() {
    int idx = blockIdx.x * blockDim.x + threadIdx.x;
    if (idx >= S_LEN * (DK / 2)) return;
    int s = idx >> 5;
    int i = idx & 31;
    float freq = 1.0f / powf(10000.0f, (float)(2 * i) / 64.0f);
    float ang  = (float)s * freq;
    double a   = (double)ang;
    g_rope[idx] = make_float2((float)cos(a), (float)sin(a));
}

// ========================================================================
// bf16 HMMA GEMM, 2-stage cp.async pipeline (validated R15).
// Epilogue modes: 0 = fp32 store, 1 = rope + split, 2 = split.
// ========================================================================
#define GST   40960
#define GT_AH 0
#define GT_AL 10240
#define GT_BH 20480
#define GT_BL 30720

struct GemmArgs {
    const __nv_bfloat16 *Ah, *Al;
    const __nv_bfloat16 *Bh[3], *Bl[3];
    float* Cf[3];
    __nv_bfloat16 *Ch[3], *Cl[3];
    int mode[3];
};

__global__ __launch_bounds__(256) void gemm_hmma(GemmArgs args) {
    extern __shared__ char smg[];
    const uint32_t smb = smem_u32(smg);

    const int z = blockIdx.z;
    const __nv_bfloat16* Ahg = args.Ah;
    const __nv_bfloat16* Alg = args.Al;
    const __nv_bfloat16* Bhg = args.Bh[z];
    const __nv_bfloat16* Blg = args.Bl[z];
    const int mode = args.mode[z];

    const int tid  = threadIdx.x;
    const int lane = tid & 31;
    const int wid  = tid >> 5;
    const int wm   = wid >> 2;
    const int wn   = wid & 3;
    const int bm   = blockIdx.y * 128;
    const int bn   = blockIdx.x * 128;

    const int l7  = lane & 7;
    const int l8  = (lane >> 3) & 1;
    const int l16 = lane >> 4;
    const uint32_t aoff = (uint32_t)((wm * 64 + l7 + l8 * 8) * 80 + l16 * 16);
    const uint32_t boff = (uint32_t)((wn * 32 + l16 * 8 + l7) * 80 + l8 * 16);

    float acc[4][4][4];
#pragma unroll
    for (int mt = 0; mt < 4; mt++)
#pragma unroll
        for (int nt = 0; nt < 4; nt++)
#pragma unroll
            for (int e = 0; e < 4; e++) acc[mt][nt][e] = 0.f;

    const int r0 = (tid + 0)   >> 2, cg0 = (tid + 0)   & 3;
    const int r1 = (tid + 256) >> 2, cg1 = (tid + 256) & 3;
    const uint32_t so0 = (uint32_t)(r0 * 80 + cg0 * 16);
    const uint32_t so1 = (uint32_t)(r1 * 80 + cg1 * 16);

#define G_ASYNC(st, kbase)                                                    \
    do {                                                                      \
        const uint32_t sb_ = smb + (uint32_t)(st) * GST;                      \
        const size_t ga0 = (size_t)(bm + r0) * DMODEL + (kbase) + cg0 * 8;    \
        const size_t ga1 = (size_t)(bm + r1) * DMODEL + (kbase) + cg1 * 8;    \
        const size_t gb0 = (size_t)(bn + r0) * DMODEL + (kbase) + cg0 * 8;    \
        const size_t gb1 = (size_t)(bn + r1) * DMODEL + (kbase) + cg1 * 8;    \
        CP16(sb_ + GT_AH + so0, Ahg + ga0); CP16(sb_ + GT_AH + so1, Ahg + ga1); \
        CP16(sb_ + GT_AL + so0, Alg + ga0); CP16(sb_ + GT_AL + so1, Alg + ga1); \
        CP16(sb_ + GT_BH + so0, Bhg + gb0); CP16(sb_ + GT_BH + so1, Bhg + gb1); \
        CP16(sb_ + GT_BL + so0, Blg + gb0); CP16(sb_ + GT_BL + so1, Blg + gb1); \
    } while (0)

    G_ASYNC(0, 0);
    CP_COMMIT();

    for (int c = 0; c < 32; c++) {
        const bool more = (c < 31);
        if (more) {
            G_ASYNC((c + 1) & 1, (c + 1) * 32);
            CP_COMMIT();
            CP_WAIT1();
        } else {
            CP_WAIT0();
        }
        __syncthreads();
        const uint32_t sb = smb + (uint32_t)(c & 1) * GST;

#pragma unroll
        for (int ks = 0; ks < 2; ks++) {
            const uint32_t kso = ks * 32;
            uint32_t Ahf[4][4], Alf[4][4], Bhf[4][2], Blf[4][2];
#pragma unroll
            for (int mt = 0; mt < 4; mt++) {
                const uint32_t ao = aoff + mt * (16 * 80) + kso;
                ldmat4(Ahf[mt], sb + GT_AH + ao);
                ldmat4(Alf[mt], sb + GT_AL + ao);
            }
#pragma unroll
            for (int np = 0; np < 2; np++) {
                const uint32_t bo = boff + np * (16 * 80) + kso;
                uint32_t t[4];
                ldmat4(t, sb + GT_BH + bo);
                Bhf[np * 2][0] = t[0]; Bhf[np * 2][1] = t[1];
                Bhf[np * 2 + 1][0] = t[2]; Bhf[np * 2 + 1][1] = t[3];
                ldmat4(t, sb + GT_BL + bo);
                Blf[np * 2][0] = t[0]; Blf[np * 2][1] = t[1];
                Blf[np * 2 + 1][0] = t[2]; Blf[np * 2 + 1][1] = t[3];
            }
#pragma unroll
            for (int mt = 0; mt < 4; mt++)
#pragma unroll
                for (int nt = 0; nt < 4; nt++) {
                    mma_bf16(acc[mt][nt], Ahf[mt], Bhf[nt]);
                    mma_bf16(acc[mt][nt], Ahf[mt], Blf[nt]);
                    mma_bf16(acc[mt][nt], Alf[mt], Bhf[nt]);
                }
        }
        __syncthreads();
    }

    const int g   = lane >> 2;
    const int tig = lane & 3;
#pragma unroll
    for (int mt = 0; mt < 4; mt++) {
        const int row = bm + wm * 64 + mt * 16 + g;
#pragma unroll
        for (int nt = 0; nt < 4; nt++) {
            const int col = bn + wn * 32 + nt * 8 + tig * 2;
            float e0 = acc[mt][nt][0], o0 = acc[mt][nt][1];
            float e1 = acc[mt][nt][2], o1 = acc[mt][nt][3];
            if (mode == 0) {
                *(float2*)(args.Cf[z] + (size_t)row * DMODEL + col) =
                    make_float2(e0, o0);
                *(float2*)(args.Cf[z] + (size_t)(row + 8) * DMODEL + col) =
                    make_float2(e1, o1);
            } else {
                if (mode == 1) {
                    const int i = (col & 63) >> 1;
                    float2 c0 = g_rope[((row & (S_LEN - 1)) << 5) + i];
                    float2 c1 = g_rope[(((row + 8) & (S_LEN - 1)) << 5) + i];
                    float te = e0 * c0.x - o0 * c0.y;
                    o0 = e0 * c0.y + o0 * c0.x; e0 = te;
                    te = e1 * c1.x - o1 * c1.y;
                    o1 = e1 * c1.y + o1 * c1.x; e1 = te;
                }
                __nv_bfloat16 he0 = __float2bfloat16_rn(e0);
                __nv_bfloat16 ho0 = __float2bfloat16_rn(o0);
                __nv_bfloat16 he1 = __float2bfloat16_rn(e1);
                __nv_bfloat16 ho1 = __float2bfloat16_rn(o1);
                uint32_t* H = (uint32_t*)(args.Ch[z] + (size_t)row * DMODEL + col);
                uint32_t* L = (uint32_t*)(args.Cl[z] + (size_t)row * DMODEL + col);
                *H = pack_bf16(he0, ho0);
                *L = pack_bf16f(e0 - __bfloat162float(he0),
                                o0 - __bfloat162float(ho0));
                H = (uint32_t*)(args.Ch[z] + (size_t)(row + 8) * DMODEL + col);
                L = (uint32_t*)(args.Cl[z] + (size_t)(row + 8) * DMODEL + col);
                *H = pack_bf16(he1, ho1);
                *L = pack_bf16f(e1 - __bfloat162float(he1),
                                o1 - __bfloat162float(ho1));
            }
        }
    }
#undef G_ASYNC
}

// ========================================================================
// Flash attention, bf16 HMMA 3-term, causal. BM=BN=64, 128 thr (4 warps).
// Byte-identical to the 575.7us round-12 kernel.
// ========================================================================
#define FLDB 144   // bytes per smem tile row (72 bf16)

__global__ __launch_bounds__(128) void flash_hmma(
    const __nv_bfloat16* __restrict__ Qhg, const __nv_bfloat16* __restrict__ Qlg,
    const __nv_bfloat16* __restrict__ Khg, const __nv_bfloat16* __restrict__ Klg,
    const __nv_bfloat16* __restrict__ Vhg, const __nv_bfloat16* __restrict__ Vlg,
    __nv_bfloat16* __restrict__ Ohg, __nv_bfloat16* __restrict__ Olg) {
    __shared__ __nv_bfloat16 sKh[64 * 72], sKl[64 * 72];
    __shared__ __nv_bfloat16 sVh[64 * 72], sVl[64 * 72];

    const int qt  = gridDim.x - 1 - blockIdx.x;
    const int h   = blockIdx.y;
    const int b   = blockIdx.z;
    const int tid = threadIdx.x;
    const int lane = tid & 31;
    const int w    = tid >> 5;
    const size_t base = ((size_t)b * S_LEN) * DMODEL + h * DK;
    const int q0 = qt * 64;

    const int l7  = lane & 7;
    const int l8  = (lane >> 3) & 1;
    const int l16 = lane >> 4;
    const int g   = lane >> 2;
    const int tig = lane & 3;

    const uint32_t sKh_b = smem_u32(sKh), sKl_b = smem_u32(sKl);
    const uint32_t sVh_b = smem_u32(sVh), sVl_b = smem_u32(sVl);

    // ---- stage Q through sKh/sKl, extract A-frags ----
#pragma unroll
    for (int p = 0; p < 4; p++) {
        int f = tid + p * 128;
        int r = f >> 3, c = f & 7;
        *(uint4*)((char*)sKh + r * FLDB + c * 16) =
            *(const uint4*)(Qhg + base + (size_t)(q0 + r) * DMODEL + c * 8);
        *(uint4*)((char*)sKl + r * FLDB + c * 16) =
            *(const uint4*)(Qlg + base + (size_t)(q0 + r) * DMODEL + c * 8);
    }
    __syncthreads();
    uint32_t qha[4][4], qla[4][4];
    {
        const uint32_t ao = (uint32_t)((w * 16 + l7 + l8 * 8) * FLDB + l16 * 16);
#pragma unroll
        for (int ks = 0; ks < 4; ks++) {
            ldmat4(qha[ks], sKh_b + ao + ks * 32);
            ldmat4(qla[ks], sKl_b + ao + ks * 32);
        }
    }
    __syncthreads();

    float o[8][4];
#pragma unroll
    for (int dt = 0; dt < 8; dt++)
#pragma unroll
        for (int e = 0; e < 4; e++) o[dt][e] = 0.f;
    float m0 = -INFINITY, m1 = -INFINITY, li0 = 0.f, li1 = 0.f;

    const uint32_t bo_k = (uint32_t)((l16 * 8 + l7) * FLDB + l8 * 16);
    const uint32_t bo_v = (uint32_t)((l8 * 8 + l7) * FLDB + l16 * 16);

    for (int kt = 0; kt <= qt; kt++) {
        const int k0 = kt * 64;
#pragma unroll
        for (int p = 0; p < 4; p++) {
            int f = tid + p * 128;
            int r = f >> 3, c = f & 7;
            const size_t gk = base + (size_t)(k0 + r) * DMODEL + c * 8;
            *(uint4*)((char*)sKh + r * FLDB + c * 16) = *(const uint4*)(Khg + gk);
            *(uint4*)((char*)sKl + r * FLDB + c * 16) = *(const uint4*)(Klg + gk);
            *(uint4*)((char*)sVh + r * FLDB + c * 16) = *(const uint4*)(Vhg + gk);
            *(uint4*)((char*)sVl + r * FLDB + c * 16) = *(const uint4*)(Vlg + gk);
        }
        __syncthreads();

        // ---- S = Q K^T (3-term) ----
        float s[8][4];
#pragma unroll
        for (int nt = 0; nt < 8; nt++)
#pragma unroll
            for (int e = 0; e < 4; e++) s[nt][e] = 0.f;

#pragma unroll
        for (int ks = 0; ks < 4; ks++) {
#pragma unroll
            for (int np = 0; np < 4; np++) {
                uint32_t th[4], tl[4];
                const uint32_t bo = bo_k + np * (16 * FLDB) + ks * 32;
                ldmat4(th, sKh_b + bo);
                ldmat4(tl, sKl_b + bo);
                mma_bf16(s[2 * np],     qha[ks], th);
                mma_bf16(s[2 * np],     qha[ks], tl);
                mma_bf16(s[2 * np],     qla[ks], th);
                mma_bf16(s[2 * np + 1], qha[ks], th + 2);
                mma_bf16(s[2 * np + 1], qha[ks], tl + 2);
                mma_bf16(s[2 * np + 1], qla[ks], th + 2);
            }
        }

        // ---- softmax (rows 16w+g and 16w+g+8) ----
        const bool diag = (kt == qt);
        const int row0 = 16 * w + g, row1 = row0 + 8;
        float mx0 = -INFINITY, mx1 = -INFINITY;
#pragma unroll
        for (int nt = 0; nt < 8; nt++) {
            const int c0 = nt * 8 + 2 * tig;
#pragma unroll
            for (int e = 0; e < 4; e++) s[nt][e] *= 0.125f;
            if (diag) {
                if (c0     > row0) s[nt][0] = -INFINITY;
                if (c0 + 1 > row0) s[nt][1] = -INFINITY;
                if (c0     > row1) s[nt][2] = -INFINITY;
                if (c0 + 1 > row1) s[nt][3] = -INFINITY;
            }
            mx0 = fmaxf(mx0, fmaxf(s[nt][0], s[nt][1]));
            mx1 = fmaxf(mx1, fmaxf(s[nt][2], s[nt][3]));
        }
#pragma unroll
        for (int off = 1; off <= 2; off <<= 1) {
            mx0 = fmaxf(mx0, __shfl_xor_sync(0xffffffffu, mx0, off));
            mx1 = fmaxf(mx1, __shfl_xor_sync(0xffffffffu, mx1, off));
        }
        const float nm0 = fmaxf(m0, mx0), nm1 = fmaxf(m1, mx1);
        const float cr0 = __expf(m0 - nm0), cr1 = __expf(m1 - nm1);
        m0 = nm0; m1 = nm1;
        float rs0 = 0.f, rs1 = 0.f;
#pragma unroll
        for (int nt = 0; nt < 8; nt++) {
            s[nt][0] = __expf(s[nt][0] - nm0);
            s[nt][1] = __expf(s[nt][1] - nm0);
            s[nt][2] = __expf(s[nt][2] - nm1);
            s[nt][3] = __expf(s[nt][3] - nm1);
            rs0 += s[nt][0] + s[nt][1];
            rs1 += s[nt][2] + s[nt][3];
        }
#pragma unroll
        for (int off = 1; off <= 2; off <<= 1) {
            rs0 += __shfl_xor_sync(0xffffffffu, rs0, off);
            rs1 += __shfl_xor_sync(0xffffffffu, rs1, off);
        }
        li0 = li0 * cr0 + rs0;
        li1 = li1 * cr1 + rs1;
#pragma unroll
        for (int dt = 0; dt < 8; dt++) {
            o[dt][0] *= cr0; o[dt][1] *= cr0;
            o[dt][2] *= cr1; o[dt][3] *= cr1;
        }

        // ---- O += P V (3-term, P split in registers) ----
#pragma unroll
        for (int j = 0; j < 4; j++) {
            uint32_t pha[4], pla[4];
#pragma unroll
            for (int half = 0; half < 2; half++) {
                const int nt = 2 * j + half;
                __nv_bfloat16 b0 = __float2bfloat16_rn(s[nt][0]);
                __nv_bfloat16 b1 = __float2bfloat16_rn(s[nt][1]);
                __nv_bfloat16 b2 = __float2bfloat16_rn(s[nt][2]);
                __nv_bfloat16 b3 = __float2bfloat16_rn(s[nt][3]);
                pha[2 * half + 0] = pack_bf16(b0, b1);
                pha[2 * half + 1] = pack_bf16(b2, b3);
                pla[2 * half + 0] = pack_bf16f(s[nt][0] - __bfloat162float(b0),
                                               s[nt][1] - __bfloat162float(b1));
                pla[2 * half + 1] = pack_bf16f(s[nt][2] - __bfloat162float(b2),
                                               s[nt][3] - __bfloat162float(b3));
            }
#pragma unroll
            for (int np = 0; np < 4; np++) {
                uint32_t tvh[4], tvl[4];
                const uint32_t bo = bo_v + j * (16 * FLDB) + np * 32;
                ldmat4t(tvh, sVh_b + bo);
                ldmat4t(tvl, sVl_b + bo);
                mma_bf16(o[2 * np],     pha, tvh);
                mma_bf16(o[2 * np],     pha, tvl);
                mma_bf16(o[2 * np],     pla, tvh);
                mma_bf16(o[2 * np + 1], pha, tvh + 2);
                mma_bf16(o[2 * np + 1], pha, tvl + 2);
                mma_bf16(o[2 * np + 1], pla, tvh + 2);
            }
        }
        __syncthreads();
    }

    // ---- epilogue: normalize + bf16 hi/lo split store ----
    const float inv0 = 1.0f / li0, inv1 = 1.0f / li1;
    const int row0 = q0 + 16 * w + g;
#pragma unroll
    for (int dt = 0; dt < 8; dt++) {
        const int col = dt * 8 + tig * 2;
        float e0 = o[dt][0] * inv0, o0 = o[dt][1] * inv0;
        float e1 = o[dt][2] * inv1, o1 = o[dt][3] * inv1;
        __nv_bfloat16 he0 = __float2bfloat16_rn(e0);
        __nv_bfloat16 ho0 = __float2bfloat16_rn(o0);
        __nv_bfloat16 he1 = __float2bfloat16_rn(e1);
        __nv_bfloat16 ho1 = __float2bfloat16_rn(o1);
        *(uint32_t*)(Ohg + base + (size_t)row0 * DMODEL + col) =
            pack_bf16(he0, ho0);
        *(uint32_t*)(Olg + base + (size_t)row0 * DMODEL + col) =
            pack_bf16f(e0 - __bfloat162float(he0), o0 - __bfloat162float(ho0));
        *(uint32_t*)(Ohg + base + (size_t)(row0 + 8) * DMODEL + col) =
            pack_bf16(he1, ho1);
        *(uint32_t*)(Olg + base + (size_t)(row0 + 8) * DMODEL + col) =
            pack_bf16f(e1 - __bfloat162float(he1), o1 - __bfloat162float(ho1));
    }
}

// ========================================================================
extern "C" void kernel_launch(void* const* d_in, const int* in_sizes, int n_in,
                              void* d_out, int out_size) {
    (void)in_sizes; (void)n_in; (void)out_size;
    const float* x  = (const float*)d_in[0];
    const float* W[4] = {(const float*)d_in[1], (const float*)d_in[2],
                         (const float*)d_in[3], (const float*)d_in[4]};
    float* out = (float*)d_out;

    __nv_bfloat16 *xh, *xl, *qh, *ql, *kh, *kl, *vh, *vl, *oh, *ol, *wh, *wl;
    cudaGetSymbolAddress((void**)&xh, g_xh);
    cudaGetSymbolAddress((void**)&xl, g_xl);
    cudaGetSymbolAddress((void**)&qh, g_qh);
    cudaGetSymbolAddress((void**)&ql, g_ql);
    cudaGetSymbolAddress((void**)&kh, g_kh);
    cudaGetSymbolAddress((void**)&kl, g_kl);
    cudaGetSymbolAddress((void**)&vh, g_vh);
    cudaGetSymbolAddress((void**)&vl, g_vl);
    cudaGetSymbolAddress((void**)&oh, g_oh);
    cudaGetSymbolAddress((void**)&ol, g_ol);
    cudaGetSymbolAddress((void**)&wh, g_wh);
    cudaGetSymbolAddress((void**)&wl, g_wl);

    const int NX4 = MTOT * DMODEL / 4;
    const int NW4 = DMODEL * DMODEL / 4;
    split_kernel<<<NX4 / 256, 256>>>(x, xh, xl, NX4);
    Split4Args sp;
    for (int i = 0; i < 4; i++) {
        sp.src[i] = W[i];
        sp.hi[i]  = wh + (size_t)i * DMODEL * DMODEL;
        sp.lo[i]  = wl + (size_t)i * DMODEL * DMODEL;
    }
    split4_kernel<<<dim3(NW4 / 256, 4), 256>>>(sp, NW4);
    rope_table_kernel<<<(S_LEN * (DK / 2) + 255) / 256, 256>>>();

    cudaFuncSetAttribute(gemm_hmma,
                         cudaFuncAttributeMaxDynamicSharedMemorySize, 2 * GST);

    GemmArgs qkv = {};
    qkv.Ah = xh; qkv.Al = xl;
    for (int i = 0; i < 3; i++) {
        qkv.Bh[i] = wh + (size_t)i * DMODEL * DMODEL;
        qkv.Bl[i] = wl + (size_t)i * DMODEL * DMODEL;
    }
    qkv.Ch[0] = qh; qkv.Cl[0] = ql; qkv.mode[0] = 1;
    qkv.Ch[1] = kh; qkv.Cl[1] = kl; qkv.mode[1] = 1;
    qkv.Ch[2] = vh; qkv.Cl[2] = vl; qkv.mode[2] = 2;
    dim3 gq(DMODEL / 128, MTOT / 128, 3);
    gemm_hmma<<<gq, 256, 2 * GST>>>(qkv);

    flash_hmma<<<dim3(S_LEN / 64, NHEADS, BATCH), 128>>>(qh, ql, kh, kl,
                                                         vh, vl, oh, ol);

    GemmArgs op = {};
    op.Ah = oh; op.Al = ol;
    op.Bh[0] = wh + 3 * (size_t)DMODEL * DMODEL;
    op.Bl[0] = wl + 3 * (size_t)DMODEL * DMODEL;
    op.Cf[0] = out; op.mode[0] = 0;
    dim3 go(DMODEL / 128, MTOT / 128, 1);
    gemm_hmma<<<go, 256, 2 * GST>>>(op);
}